// round 16
// baseline (speedup 1.0000x reference)
#include <cuda_runtime.h>
#include <math.h>
#include <stdint.h>

// DeFeat distillation loss — bf16 m16n8k16 mma.sync, ldmatrix A, all 5 levels,
// fused deterministic finalize. BN=32 tiles for 3 blocks/SM occupancy.
// B=8, C=256, sizes {128,64,32,16,8}, strides {8..128}, 16 boxes.
//
// Per block: D[256 x 32] = W[256 x 256] * fs[256 x 32]
//   A: W pre-packed bf16 [m][kpair], cp.async double-buffered (BK=32), ldmatrix.x4
//   B: fs fp32 -> bf16 pairs via regs (LDG+cvt+STS), double-buffered
//   8 warps, warp w -> rows [32w, 32w+32), all 32 positions.

#define CC    256
#define NBOX  16
#define BM    256
#define BN    32
#define BK    32
#define KP2   16              // k-pairs per stage
#define NIT   8               // CC / BK
#define ASTR  20              // A smem row stride in b32 (16 data + 4 pad; mult of 4 -> cp16 OK)
#define BSTR  40              // B smem row stride in b32 (32 data + 8 pad)

#define A_STAGE_W (BM * ASTR)        // 5120 b32
#define B_STAGE_W (KP2 * BSTR)       // 640 b32
#define DSMEM_BYTES ((2 * A_STAGE_W + 2 * B_STAGE_W) * 4)   // 46080

#define TOTAL_BLOCKS 5456

__device__ float g_part_gt[5472];
__device__ float g_part_bg[5472];
__device__ unsigned int g_count = 0;
__device__ uint32_t g_Wbf[5][CC * (CC / 2)];   // [lvl][m][kpair] packed bf16x2

struct LevelPtrs { const float *fs, *ft, *Wm, *bias; };
struct KP { LevelPtrs lv[5]; const float* boxes; };

__device__ __forceinline__ uint32_t smem_u32(const void* p) {
    uint32_t a;
    asm("{ .reg .u64 t; cvta.to.shared.u64 t, %1; cvt.u32.u64 %0, t; }" : "=r"(a) : "l"(p));
    return a;
}
__device__ __forceinline__ void cp16(void* smem_dst, const void* gmem_src) {
    uint32_t d = (uint32_t)__cvta_generic_to_shared(smem_dst);
    asm volatile("cp.async.cg.shared.global [%0], [%1], 16;\n" :: "r"(d), "l"(gmem_src));
}
__device__ __forceinline__ void cp_commit() { asm volatile("cp.async.commit_group;\n"); }
template<int N> __device__ __forceinline__ void cp_wait() { asm volatile("cp.async.wait_group %0;\n" :: "n"(N)); }

// r = {hi = b, lo = a}
__device__ __forceinline__ uint32_t packbf(float a, float b) {
    uint32_t r;
    asm("cvt.rn.bf16x2.f32 %0, %1, %2;" : "=r"(r) : "f"(b), "f"(a));
    return r;
}
__device__ __forceinline__ void ldmx4(uint32_t r[4], uint32_t addr) {
    asm volatile("ldmatrix.sync.aligned.m8n8.x4.shared.b16 {%0,%1,%2,%3}, [%4];"
        : "=r"(r[0]), "=r"(r[1]), "=r"(r[2]), "=r"(r[3]) : "r"(addr));
}
__device__ __forceinline__ void mma_k16(float c[4], const uint32_t a[4],
                                        uint32_t b0, uint32_t b1) {
    asm volatile(
        "mma.sync.aligned.m16n8k16.row.col.f32.bf16.bf16.f32 "
        "{%0,%1,%2,%3}, {%4,%5,%6,%7}, {%8,%9}, {%0,%1,%2,%3};\n"
        : "+f"(c[0]), "+f"(c[1]), "+f"(c[2]), "+f"(c[3])
        : "r"(a[0]), "r"(a[1]), "r"(a[2]), "r"(a[3]), "r"(b0), "r"(b1));
}

// ---- prep: pack W fp32 [m][k] -> bf16x2 [m][kpair]. grid (128,5) x 256 ----
__global__ void defeat_prep_kernel(KP P)
{
    int lvl = blockIdx.y;
    int idx = blockIdx.x * 256 + threadIdx.x;
    const float2 w2 = *(const float2*)(P.lv[lvl].Wm + (size_t)idx * 2);
    g_Wbf[lvl][idx] = packbf(w2.x, w2.y);
}

// ---- main kernel ----
__global__ __launch_bounds__(256, 3)
void defeat_main_kernel(KP P, float* out)
{
    extern __shared__ __align__(16) uint32_t dsmem[];
    uint32_t* Asm = dsmem;                       // 2 stages of A
    uint32_t* Bsm = dsmem + 2 * A_STAGE_W;       // 2 stages of B
    __shared__ float mask_s[BN];
    __shared__ float boxes_s[NBOX * 4];
    __shared__ float red[16];
    __shared__ float fred[256];
    __shared__ unsigned s_last;

    const int tid  = threadIdx.x;
    const int warp = tid >> 5, lane = tid & 31;
    const int bid  = blockIdx.x;

    // ---- decode level + tile ----
    int lvl, base;
    if      (bid < 4096) { lvl = 0; base = 0;    }
    else if (bid < 5120) { lvl = 1; base = 4096; }
    else if (bid < 5376) { lvl = 2; base = 5120; }
    else if (bid < 5440) { lvl = 3; base = 5376; }
    else                 { lvl = 4; base = 5440; }

    const int H      = 128 >> lvl;
    const int stride = 8 << lvl;
    const int HW     = H * H;
    const int nTN    = HW >> 5;          // tiles of 32 positions
    const int rel    = bid - base;
    const int b      = rel / nTN;
    const int nTile  = rel - b * nTN;
    const int posBase = nTile * BN;

    const float* fsb  = P.lv[lvl].fs + (size_t)b * CC * HW;
    const float* ftb  = P.lv[lvl].ft + (size_t)b * CC * HW;
    const float* bias = P.lv[lvl].bias;
    const uint32_t* WbfL = g_Wbf[lvl];

    if (tid < NBOX * 4)
        boxes_s[tid] = P.boxes[(size_t)b * NBOX * 4 + tid];
    __syncthreads();

    // ---- rasterize GT mask for this block's 32 positions ----
    if (tid < BN) {
        int pos = posBase + tid;
        int y = pos / H, x = pos - y * H;
        float m = 0.f;
        float inv = 1.0f / (float)stride;
        #pragma unroll 1
        for (int n = 0; n < NBOX; n++) {
            int lx = min((int)floorf(boxes_s[n*4+0] * inv), H - 1);
            int ly = min((int)floorf(boxes_s[n*4+1] * inv), H - 1);
            int rx = min((int)floorf(boxes_s[n*4+2] * inv), H - 1);
            int ry = min((int)floorf(boxes_s[n*4+3] * inv), H - 1);
            bool hit;
            if (lx == rx || ly == ry) hit = (y == ly) && (x == lx);
            else                      hit = (y >= ly) && (y < ry) && (x >= lx) && (x < rx);
            if (hit) { m = 1.f; break; }
        }
        mask_s[tid] = m;
    }

    // ---- A loader: cp.async, 256 rows x 16 b32 per stage (1024 chunks, 4/thread) ----
    auto cpA = [&](int it) {
        uint32_t* ab = Asm + (it & 1) * A_STAGE_W;
        const int kp0 = it * KP2;
        #pragma unroll
        for (int i = 0; i < 4; i++) {
            int c = tid + i * 256;
            int m = c >> 2, j = c & 3;
            cp16(ab + m * ASTR + j * 4, WbfL + (size_t)m * (CC / 2) + kp0 + j * 4);
        }
    };

    // ---- B loader: threads 0..127, 1 chunk each. kp = tid>>3, jc = tid&7 ----
    float4 br0, br1;
    const int b_kp = tid >> 3;          // 0..31 (only <16 used when tid<128)
    const int b_jc = tid & 7;           // 0..7
    auto ldgB = [&](int it) {
        if (tid < 128) {
            const float* p0 = fsb + (size_t)(it * BK + 2 * b_kp) * HW + posBase + b_jc * 4;
            br0 = *(const float4*)p0;
            br1 = *(const float4*)(p0 + HW);
        }
    };
    auto stsB = [&](int it) {
        if (tid < 128) {
            uint32_t* bb = Bsm + (it & 1) * B_STAGE_W;
            uint4 u;
            u.x = packbf(br0.x, br1.x);
            u.y = packbf(br0.y, br1.y);
            u.z = packbf(br0.z, br1.z);
            u.w = packbf(br0.w, br1.w);
            *(uint4*)(bb + b_kp * BSTR + b_jc * 4) = u;
        }
    };

    // ---- warp layout: warp w -> rows [32w, 32w+32), all 32 positions ----
    const int gid = lane >> 2, tg = lane & 3;
    const int M0 = warp * 32;

    const uint32_t asm_u32 = smem_u32(Asm);
    const uint32_t a_lane_off = (uint32_t)(((M0 + (lane & 15)) * ASTR + ((lane >> 4) << 2)) * 4);

    float acc[2][4][4];
    #pragma unroll
    for (int mt = 0; mt < 2; mt++)
        #pragma unroll
        for (int nt = 0; nt < 4; nt++)
            #pragma unroll
            for (int r = 0; r < 4; r++) acc[mt][nt][r] = 0.f;

    // ---- prologue ----
    cpA(0); cp_commit();
    ldgB(0);
    cpA(1); cp_commit();
    stsB(0);
    cp_wait<1>();           // A(0) done; A(1) in flight
    __syncthreads();

    // ---- main loop: 8 iterations of BK=32 ----
    for (int it = 0; it < NIT; it++) {
        const uint32_t abase = asm_u32 + (uint32_t)((it & 1) * A_STAGE_W * 4);
        const uint32_t* bb = Bsm + (it & 1) * B_STAGE_W;

        if (it + 1 < NIT) ldgB(it + 1);

        #pragma unroll
        for (int s = 0; s < 2; s++) {               // k16 steps; kpair offset s*8
            const int qb = s * 8;
            uint32_t afr[2][4], bfr[4][2];
            #pragma unroll
            for (int mt = 0; mt < 2; mt++)
                ldmx4(afr[mt], abase + a_lane_off + (uint32_t)((mt * 16 * ASTR + qb) * 4));
            #pragma unroll
            for (int nt = 0; nt < 4; nt++) {
                int nc = nt * 8 + gid;
                bfr[nt][0] = bb[(qb + tg    ) * BSTR + nc];
                bfr[nt][1] = bb[(qb + tg + 4) * BSTR + nc];
            }
            #pragma unroll
            for (int mt = 0; mt < 2; mt++)
                #pragma unroll
                for (int nt = 0; nt < 4; nt++)
                    mma_k16(acc[mt][nt], afr[mt], bfr[nt][0], bfr[nt][1]);
        }

        if (it + 1 < NIT) {
            stsB(it + 1);
            if (it + 2 < NIT) { cpA(it + 2); cp_commit(); cp_wait<1>(); }
            else              { cp_wait<0>(); }
        }
        __syncthreads();
    }

    // ---- epilogue: masked squared diff vs feat_t ----
    float sgt = 0.f, sbg = 0.f;
    #pragma unroll
    for (int mt = 0; mt < 2; mt++) {
        #pragma unroll
        for (int h = 0; h < 2; h++) {
            int row = M0 + mt * 16 + gid + 8 * h;
            float bv = bias[row];
            #pragma unroll
            for (int nt = 0; nt < 4; nt++) {
                int colL = nt * 8 + 2 * tg;
                float2 t2 = *(const float2*)&ftb[(size_t)row * HW + posBase + colL];
                float a0 = acc[mt][nt][2*h + 0] + bv;
                float a1 = acc[mt][nt][2*h + 1] + bv;
                float d0 = t2.x - a0, d1 = t2.y - a1;
                float m0 = mask_s[colL], m1 = mask_s[colL + 1];
                float q0 = d0 * d0, q1 = d1 * d1;
                sgt += q0 * m0 + q1 * m1;
                sbg += q0 * (1.f - m0) + q1 * (1.f - m1);
            }
        }
    }

    // ---- deterministic block reduction ----
    #pragma unroll
    for (int off = 16; off > 0; off >>= 1) {
        sgt += __shfl_down_sync(0xffffffffu, sgt, off);
        sbg += __shfl_down_sync(0xffffffffu, sbg, off);
    }
    if (lane == 0) { red[warp] = sgt; red[warp + 8] = sbg; }
    __syncthreads();
    if (tid == 0) {
        float g = 0.f, bg = 0.f;
        #pragma unroll
        for (int w2 = 0; w2 < 8; w2++) { g += red[w2]; bg += red[w2 + 8]; }
        g_part_gt[bid] = g;
        g_part_bg[bid] = bg;
        __threadfence();
        unsigned t = atomicAdd(&g_count, 1u);
        s_last = (t == TOTAL_BLOCKS - 1) ? 1u : 0u;
    }
    __syncthreads();

    // ---- last block: deterministic finalize ----
    if (s_last) {
        __threadfence();
        const int counts[5] = {4096, 1024, 256, 64, 16};
        float loss = 0.f;
        int off = 0;
        for (int L = 0; L < 5; L++) {
            float g = 0.f, bg = 0.f;
            for (int i = tid; i < counts[L]; i += 256) g  += g_part_gt[off + i];
            for (int i = tid; i < counts[L]; i += 256) bg += g_part_bg[off + i];

            fred[tid] = g; __syncthreads();
            for (int s = 128; s > 0; s >>= 1) { if (tid < s) fred[tid] += fred[tid + s]; __syncthreads(); }
            float gs = fred[0]; __syncthreads();

            fred[tid] = bg; __syncthreads();
            for (int s = 128; s > 0; s >>= 1) { if (tid < s) fred[tid] += fred[tid + s]; __syncthreads(); }
            float bgs = fred[0]; __syncthreads();

            loss += 0.004f * sqrtf(gs + 1e-8f) + 0.0002f * sqrtf(bgs + 1e-8f);
            off += counts[L];
            __syncthreads();
        }
        if (tid == 0) {
            out[0] = loss;
            g_count = 0;     // reset for next graph replay
        }
    }
}

extern "C" void kernel_launch(void* const* d_in, const int* in_sizes, int n_in,
                              void* d_out, int out_size)
{
    (void)in_sizes; (void)n_in; (void)out_size;
    KP P;
    for (int i = 0; i < 5; i++) {
        P.lv[i].fs   = (const float*)d_in[4 * i + 0];
        P.lv[i].ft   = (const float*)d_in[4 * i + 1];
        P.lv[i].Wm   = (const float*)d_in[4 * i + 2];
        P.lv[i].bias = (const float*)d_in[4 * i + 3];
    }
    P.boxes = (const float*)d_in[20];

    dim3 pg(128, 5);
    defeat_prep_kernel<<<pg, 256>>>(P);

    cudaFuncSetAttribute(defeat_main_kernel,
                         cudaFuncAttributeMaxDynamicSharedMemorySize, DSMEM_BYTES);
    defeat_main_kernel<<<TOTAL_BLOCKS, 256, DSMEM_BYTES>>>(P, (float*)d_out);
}

// round 17
// speedup vs baseline: 1.4420x; 1.4420x over previous
#include <cuda_runtime.h>
#include <math.h>
#include <stdint.h>

// DeFeat distillation loss — bf16 m16n8k16 mma.sync, ldmatrix A, all 5 levels,
// fused deterministic finalize. R10 structure + ft cp.async prefetch into dead
// A-smem + mask/bias hoisting + full mainloop unroll.
// B=8, C=256, sizes {128,64,32,16,8}, strides {8..128}, 16 boxes.
//
// Per block: D[256 x 64] = W[256 x 256] * fs[256 x 64]
//   A: W pre-packed bf16 [m][kpair], cp.async double-buffered (BK=64), ldmatrix.x4
//   B: fs fp32 -> bf16 pairs via regs (LDG+cvt+STS), double-buffered
//   ft: fp32 cp.async into the A stages once they are dead (stage0 during last
//       iter, stage1 after the loop) -> epilogue reads smem, not DRAM-latency.

#define CC    256
#define NBOX  16
#define BM    256
#define BN    64
#define BK    64
#define KP2   32              // k-pairs per stage
#define NIT   4               // CC / BK
#define ASTR  36              // A smem row stride in b32 (32 data + 4 pad)
#define BSTR  72              // B smem row stride in b32 (64 data + 8 pad)
#define FSTR  68              // ft smem row stride in b32 (64 data + 4 pad; mult of 4)

#define A_STAGE_W (BM * ASTR)        // 9216 b32
#define B_STAGE_W (KP2 * BSTR)       // 2304 b32
#define DSMEM_BYTES ((2 * A_STAGE_W + 2 * B_STAGE_W) * 4)   // 92160

#define TOTAL_BLOCKS 2728

__device__ float g_part_gt[2752];
__device__ float g_part_bg[2752];
__device__ unsigned int g_count = 0;
__device__ uint32_t g_Wbf[5][CC * (CC / 2)];   // [lvl][m][kpair] packed bf16x2

struct LevelPtrs { const float *fs, *ft, *Wm, *bias; };
struct KP { LevelPtrs lv[5]; const float* boxes; };

__device__ __forceinline__ uint32_t smem_u32(const void* p) {
    uint32_t a;
    asm("{ .reg .u64 t; cvta.to.shared.u64 t, %1; cvt.u32.u64 %0, t; }" : "=r"(a) : "l"(p));
    return a;
}
__device__ __forceinline__ void cp16(void* smem_dst, const void* gmem_src) {
    uint32_t d = (uint32_t)__cvta_generic_to_shared(smem_dst);
    asm volatile("cp.async.cg.shared.global [%0], [%1], 16;\n" :: "r"(d), "l"(gmem_src));
}
__device__ __forceinline__ void cp_commit() { asm volatile("cp.async.commit_group;\n"); }
template<int N> __device__ __forceinline__ void cp_wait() { asm volatile("cp.async.wait_group %0;\n" :: "n"(N)); }

// r = {hi = b, lo = a}
__device__ __forceinline__ uint32_t packbf(float a, float b) {
    uint32_t r;
    asm("cvt.rn.bf16x2.f32 %0, %1, %2;" : "=r"(r) : "f"(b), "f"(a));
    return r;
}
__device__ __forceinline__ void ldmx4(uint32_t r[4], uint32_t addr) {
    asm volatile("ldmatrix.sync.aligned.m8n8.x4.shared.b16 {%0,%1,%2,%3}, [%4];"
        : "=r"(r[0]), "=r"(r[1]), "=r"(r[2]), "=r"(r[3]) : "r"(addr));
}
__device__ __forceinline__ void mma_k16(float c[4], const uint32_t a[4],
                                        uint32_t b0, uint32_t b1) {
    asm volatile(
        "mma.sync.aligned.m16n8k16.row.col.f32.bf16.bf16.f32 "
        "{%0,%1,%2,%3}, {%4,%5,%6,%7}, {%8,%9}, {%0,%1,%2,%3};\n"
        : "+f"(c[0]), "+f"(c[1]), "+f"(c[2]), "+f"(c[3])
        : "r"(a[0]), "r"(a[1]), "r"(a[2]), "r"(a[3]), "r"(b0), "r"(b1));
}

// ---- prep: pack W fp32 [m][k] -> bf16x2 [m][kpair]. grid (128,5) x 256 ----
__global__ void defeat_prep_kernel(KP P)
{
    int lvl = blockIdx.y;
    int idx = blockIdx.x * 256 + threadIdx.x;
    const float2 w2 = *(const float2*)(P.lv[lvl].Wm + (size_t)idx * 2);
    g_Wbf[lvl][idx] = packbf(w2.x, w2.y);
}

// ---- main kernel ----
__global__ __launch_bounds__(256, 2)
void defeat_main_kernel(KP P, float* out)
{
    extern __shared__ __align__(16) uint32_t dsmem[];
    uint32_t* Asm = dsmem;                       // 2 stages of A (later: ft fp32)
    uint32_t* Bsm = dsmem + 2 * A_STAGE_W;       // 2 stages of B
    __shared__ float mask_s[BN];
    __shared__ float boxes_s[NBOX * 4];
    __shared__ float bias_s[256];
    __shared__ float red[256];
    __shared__ unsigned s_last;

    const int tid  = threadIdx.x;
    const int warp = tid >> 5, lane = tid & 31;
    const int bid  = blockIdx.x;

    // ---- decode level + tile ----
    int lvl, base;
    if      (bid < 2048) { lvl = 0; base = 0;    }
    else if (bid < 2560) { lvl = 1; base = 2048; }
    else if (bid < 2688) { lvl = 2; base = 2560; }
    else if (bid < 2720) { lvl = 3; base = 2688; }
    else                 { lvl = 4; base = 2720; }

    const int H      = 128 >> lvl;
    const int stride = 8 << lvl;
    const int HW     = H * H;
    const int nTN    = HW >> 6;
    const int rel    = bid - base;
    const int b      = rel / nTN;
    const int nTile  = rel - b * nTN;
    const int posBase = nTile * BN;

    const float* fsb  = P.lv[lvl].fs + (size_t)b * CC * HW;
    const float* ftb  = P.lv[lvl].ft + (size_t)b * CC * HW;
    const uint32_t* WbfL = g_Wbf[lvl];

    if (tid < NBOX * 4)
        boxes_s[tid] = P.boxes[(size_t)b * NBOX * 4 + tid];
    bias_s[tid] = P.lv[lvl].bias[tid];
    __syncthreads();

    // ---- rasterize GT mask for this block's 64 positions ----
    if (tid < BN) {
        int pos = posBase + tid;
        int y = pos / H, x = pos - y * H;
        float m = 0.f;
        float inv = 1.0f / (float)stride;
        #pragma unroll 1
        for (int n = 0; n < NBOX; n++) {
            int lx = min((int)floorf(boxes_s[n*4+0] * inv), H - 1);
            int ly = min((int)floorf(boxes_s[n*4+1] * inv), H - 1);
            int rx = min((int)floorf(boxes_s[n*4+2] * inv), H - 1);
            int ry = min((int)floorf(boxes_s[n*4+3] * inv), H - 1);
            bool hit;
            if (lx == rx || ly == ry) hit = (y == ly) && (x == lx);
            else                      hit = (y >= ly) && (y < ry) && (x >= lx) && (x < rx);
            if (hit) { m = 1.f; break; }
        }
        mask_s[tid] = m;
    }

    // ---- A loader: cp.async, 256 rows x 32 b32 per stage (2048 chunks, 8/thread) ----
    auto cpA = [&](int it) {
        uint32_t* ab = Asm + (it & 1) * A_STAGE_W;
        const int kp0 = it * KP2;
        #pragma unroll
        for (int i = 0; i < 8; i++) {
            int c = tid + i * 256;
            int m = c >> 3, j = c & 7;
            cp16(ab + m * ASTR + j * 4, WbfL + (size_t)m * (CC / 2) + kp0 + j * 4);
        }
    };

    // ---- B loader: LDG fp32 pairs -> cvt.rn.bf16x2 -> STS (1 item/thread) ----
    float4 br0, br1;
    const int b_kp = tid >> 4;          // 0..15
    const int b_j  = tid & 15;          // 0..15
    auto ldgB = [&](int it) {
        const float* p0 = fsb + (size_t)(it * (BK / 2) * 2 + 2 * b_kp * 2) * HW
                              + posBase + b_j * 4;
        // NOTE: BK=64 -> k0 = it*64, kpair pitch 2 rows; item covers kpairs (2*b_kp, 2*b_kp+1)? No:
        (void)p0;
    };
    (void)ldgB; // replaced below (kept lambda slot minimal)

    // Correct B loader (as in R10): 512 b32 items per stage, 2 items/thread.
    float4 brA0, brA1, brB0, brB1;
    auto ldgB2 = [&](int it) {
        const int k0 = it * BK;
        {
            int w2 = tid;
            int kp = w2 >> 4, j = w2 & 15;
            const float* p0 = fsb + (size_t)(k0 + 2 * kp) * HW + posBase + j * 4;
            brA0 = *(const float4*)p0;
            brA1 = *(const float4*)(p0 + HW);
        }
        {
            int w2 = tid + 256;
            int kp = w2 >> 4, j = w2 & 15;
            const float* p0 = fsb + (size_t)(k0 + 2 * kp) * HW + posBase + j * 4;
            brB0 = *(const float4*)p0;
            brB1 = *(const float4*)(p0 + HW);
        }
    };
    auto stsB2 = [&](int it) {
        uint32_t* bb = Bsm + (it & 1) * B_STAGE_W;
        {
            int w2 = tid;
            int kp = w2 >> 4, j = w2 & 15;
            uint4 u;
            u.x = packbf(brA0.x, brA1.x);
            u.y = packbf(brA0.y, brA1.y);
            u.z = packbf(brA0.z, brA1.z);
            u.w = packbf(brA0.w, brA1.w);
            *(uint4*)(bb + kp * BSTR + j * 4) = u;
        }
        {
            int w2 = tid + 256;
            int kp = w2 >> 4, j = w2 & 15;
            uint4 u;
            u.x = packbf(brB0.x, brB1.x);
            u.y = packbf(brB0.y, brB1.y);
            u.z = packbf(brB0.z, brB1.z);
            u.w = packbf(brB0.w, brB1.w);
            *(uint4*)(bb + kp * BSTR + j * 4) = u;
        }
    };

    // ---- ft loader: cp.async fp32 into dead A stages. 4096 chunks, 16/thread ----
    // chunk c: chan = c>>4, j = c&15; smem word = seg*A_STAGE_W + (chan&127)*FSTR + j*4
    auto cpFT = [&](int i0, int i1) {
        #pragma unroll
        for (int i = 0; i < 16; i++) {
            if (i < i0 || i >= i1) continue;
            int c = tid + i * 256;
            int chan = c >> 4, j = c & 15;
            int seg = chan >> 7;
            int r   = chan & 127;
            cp16(Asm + seg * A_STAGE_W + r * FSTR + j * 4,
                 ftb + (size_t)chan * HW + posBase + j * 4);
        }
    };

    // ---- warp layout: 8 warps = 4(m) x 2(n); warp tile 64m x 32n ----
    const int wm = warp >> 1, wn = warp & 1;
    const int gid = lane >> 2, tg = lane & 3;
    const int M0 = wm * 64;
    const int N0 = wn * 32;

    const uint32_t asm_u32 = smem_u32(Asm);
    const uint32_t a_lane_off = (uint32_t)(((M0 + (lane & 15)) * ASTR + ((lane >> 4) << 2)) * 4);

    float acc[4][4][4];
    #pragma unroll
    for (int mt = 0; mt < 4; mt++)
        #pragma unroll
        for (int nt = 0; nt < 4; nt++)
            #pragma unroll
            for (int r = 0; r < 4; r++) acc[mt][nt][r] = 0.f;

    // ---- prologue ----
    cpA(0); cp_commit();
    ldgB2(0);
    cpA(1); cp_commit();
    stsB2(0);
    cp_wait<1>();           // A(0) done; A(1) in flight
    __syncthreads();

    // ---- main loop: 4 iterations of BK=64 (fully unrolled) ----
    #pragma unroll
    for (int it = 0; it < NIT; it++) {
        const uint32_t abase = asm_u32 + (uint32_t)((it & 1) * A_STAGE_W * 4);
        const uint32_t* bb = Bsm + (it & 1) * B_STAGE_W;

        if (it == NIT - 1) {            // A stage 0 is dead now: prefetch ft half 1
            cpFT(0, 8); cp_commit();
        }
        if (it + 1 < NIT) ldgB2(it + 1);

        #pragma unroll
        for (int s = 0; s < 4; s++) {               // k16 steps; kpair offset s*8
            const int qb = s * 8;
            uint32_t afr[4][4], bfr[4][2];
            #pragma unroll
            for (int mt = 0; mt < 4; mt++)
                ldmx4(afr[mt], abase + a_lane_off + (uint32_t)((mt * 16 * ASTR + qb) * 4));
            #pragma unroll
            for (int nt = 0; nt < 4; nt++) {
                int nc = N0 + nt * 8 + gid;
                bfr[nt][0] = bb[(qb + tg    ) * BSTR + nc];
                bfr[nt][1] = bb[(qb + tg + 4) * BSTR + nc];
            }
            #pragma unroll
            for (int mt = 0; mt < 4; mt++)
                #pragma unroll
                for (int nt = 0; nt < 4; nt++)
                    mma_k16(acc[mt][nt], afr[mt], bfr[nt][0], bfr[nt][1]);
        }

        if (it + 1 < NIT) {
            stsB2(it + 1);
            if (it + 2 < NIT) { cpA(it + 2); cp_commit(); cp_wait<1>(); }
            else              { cp_wait<0>(); }
        }
        __syncthreads();
    }

    // ---- ft half 2 into A stage 1 (now dead), wait all ft ----
    cpFT(8, 16); cp_commit();
    cp_wait<0>();
    __syncthreads();

    // ---- epilogue: masked squared diff vs feat_t (ft from smem fp32) ----
    float mreg[8];
    #pragma unroll
    for (int nt = 0; nt < 4; nt++) {
        mreg[2*nt]   = mask_s[N0 + nt * 8 + 2 * tg];
        mreg[2*nt+1] = mask_s[N0 + nt * 8 + 2 * tg + 1];
    }
    const float* Fts = (const float*)Asm;
    const uint32_t fwb = (M0 >= 128) ? (uint32_t)A_STAGE_W : 0u;

    float sgt = 0.f, sbg = 0.f;
    #pragma unroll
    for (int mt = 0; mt < 4; mt++) {
        #pragma unroll
        for (int h = 0; h < 2; h++) {
            int row = M0 + mt * 16 + gid + 8 * h;
            float bv = bias_s[row];
            int rw = (int)fwb + (row & 127) * FSTR;
            #pragma unroll
            for (int nt = 0; nt < 4; nt++) {
                int colL = N0 + nt * 8 + 2 * tg;
                float2 t2 = *(const float2*)&Fts[rw + colL];
                float a0 = acc[mt][nt][2*h + 0] + bv;
                float a1 = acc[mt][nt][2*h + 1] + bv;
                float d0 = t2.x - a0, d1 = t2.y - a1;
                float q0 = d0 * d0, q1 = d1 * d1;
                sgt += q0 * mreg[2*nt] + q1 * mreg[2*nt+1];
                sbg += q0 * (1.f - mreg[2*nt]) + q1 * (1.f - mreg[2*nt+1]);
            }
        }
    }

    // ---- deterministic block reduction ----
    #pragma unroll
    for (int off = 16; off > 0; off >>= 1) {
        sgt += __shfl_down_sync(0xffffffffu, sgt, off);
        sbg += __shfl_down_sync(0xffffffffu, sbg, off);
    }
    __syncthreads();
    if (lane == 0) { red[warp] = sgt; red[warp + 8] = sbg; }
    __syncthreads();
    if (tid == 0) {
        float g = 0.f, bg = 0.f;
        #pragma unroll
        for (int w2 = 0; w2 < 8; w2++) { g += red[w2]; bg += red[w2 + 8]; }
        g_part_gt[bid] = g;
        g_part_bg[bid] = bg;
        __threadfence();
        unsigned t = atomicAdd(&g_count, 1u);
        s_last = (t == TOTAL_BLOCKS - 1) ? 1u : 0u;
    }
    __syncthreads();

    // ---- last block: deterministic finalize ----
    if (s_last) {
        __threadfence();
        const int counts[5] = {2048, 512, 128, 32, 8};
        float loss = 0.f;
        int off = 0;
        for (int L = 0; L < 5; L++) {
            float g = 0.f, bg = 0.f;
            for (int i = tid; i < counts[L]; i += 256) g  += g_part_gt[off + i];
            for (int i = tid; i < counts[L]; i += 256) bg += g_part_bg[off + i];

            red[tid] = g; __syncthreads();
            for (int s = 128; s > 0; s >>= 1) { if (tid < s) red[tid] += red[tid + s]; __syncthreads(); }
            float gs = red[0]; __syncthreads();

            red[tid] = bg; __syncthreads();
            for (int s = 128; s > 0; s >>= 1) { if (tid < s) red[tid] += red[tid + s]; __syncthreads(); }
            float bgs = red[0]; __syncthreads();

            loss += 0.004f * sqrtf(gs + 1e-8f) + 0.0002f * sqrtf(bgs + 1e-8f);
            off += counts[L];
            __syncthreads();
        }
        if (tid == 0) {
            out[0] = loss;
            g_count = 0;     // reset for next graph replay
        }
    }
}

extern "C" void kernel_launch(void* const* d_in, const int* in_sizes, int n_in,
                              void* d_out, int out_size)
{
    (void)in_sizes; (void)n_in; (void)out_size;
    KP P;
    for (int i = 0; i < 5; i++) {
        P.lv[i].fs   = (const float*)d_in[4 * i + 0];
        P.lv[i].ft   = (const float*)d_in[4 * i + 1];
        P.lv[i].Wm   = (const float*)d_in[4 * i + 2];
        P.lv[i].bias = (const float*)d_in[4 * i + 3];
    }
    P.boxes = (const float*)d_in[20];

    dim3 pg(128, 5);
    defeat_prep_kernel<<<pg, 256>>>(P);

    cudaFuncSetAttribute(defeat_main_kernel,
                         cudaFuncAttributeMaxDynamicSharedMemorySize, DSMEM_BYTES);
    defeat_main_kernel<<<TOTAL_BLOCKS, 256, DSMEM_BYTES>>>(P, (float*)d_out);
}